// round 1
// baseline (speedup 1.0000x reference)
#include <cuda_runtime.h>
#include <math.h>

// Problem constants
#define NT 1024           // tokens
#define NA 2              // top-k experts per token
#define NE 8              // experts
#define NI 2816           // intermediate
#define ND 1024           // dim
#define NSLOT (NT * NA)   // 2048 (token, k) slots

// Tiling
#define TM 64             // slot-tile
#define TN 64             // out-feature tile
#define TK 16             // k tile
#define PAD 68            // smem row stride (floats): 16B-aligned rows, reduced bank conflicts

// Scratch (device globals — no allocation allowed)
__device__ int   g_count[NE];
__device__ int   g_slots[NE][NSLOT];
__device__ int   g_is64;
__device__ float g_h[(size_t)NSLOT * NI];   // 23 MB SwiGLU activations

// ---------------------------------------------------------------------------
// Detect index dtype (int64 vs int32) + zero per-expert counters.
// int64 data => every high 32-bit word of values (all in [0,8)) is zero.
// We only inspect the first 2048 int32 words (always within the buffer).
// ---------------------------------------------------------------------------
__global__ void detect_and_zero_kernel(const int* __restrict__ idx32) {
    __shared__ int any;
    if (threadIdx.x == 0) any = 0;
    if (threadIdx.x < NE) g_count[threadIdx.x] = 0;
    __syncthreads();
    int local = 0;
    for (int i = threadIdx.x; i < NSLOT / 2; i += blockDim.x)
        local |= idx32[2 * i + 1];
    if (local) atomicOr(&any, 1);
    __syncthreads();
    if (threadIdx.x == 0) g_is64 = (any == 0) ? 1 : 0;
}

// ---------------------------------------------------------------------------
// Route: bucket slots by expert. Order within a bucket is atomics-dependent
// but the final output per slot is order-independent => deterministic result.
// ---------------------------------------------------------------------------
__global__ void route_kernel(const int* __restrict__ idx32) {
    int s = blockIdx.x * blockDim.x + threadIdx.x;
    if (s < NSLOT) {
        int e = g_is64 ? idx32[2 * s] : idx32[s];
        e &= (NE - 1);
        int p = atomicAdd(&g_count[e], 1);
        g_slots[e][p] = s;
    }
}

// ---------------------------------------------------------------------------
// GEMM1 (fused w1 & w3 + SwiGLU):
//   for each expert e, gathered token rows X[Ne, D]:
//     h = silu(X @ w1[e]^T) * (X @ w3[e]^T)   -> g_h[slot, NI]
// Block computes a 64(slots) x 64(I) tile with two B operands sharing the A tile.
// ---------------------------------------------------------------------------
__global__ __launch_bounds__(256) void gemm1_kernel(
    const float* __restrict__ x,
    const float* __restrict__ w1,
    const float* __restrict__ w3)
{
    const int e     = blockIdx.z;
    const int ne    = g_count[e];
    const int mBase = blockIdx.y * TM;
    if (mBase >= ne) return;
    const int nBase = blockIdx.x * TN;

    __shared__ __align__(16) float As [TK][PAD];
    __shared__ __align__(16) float B1s[TK][PAD];
    __shared__ __align__(16) float B3s[TK][PAD];
    __shared__ int sSlot[TM];

    const int tx  = threadIdx.x;
    const int ty  = threadIdx.y;
    const int tid = ty * 16 + tx;

    if (tid < TM) {
        int m = mBase + tid;
        sSlot[tid] = (m < ne) ? g_slots[e][m] : -1;
    }
    __syncthreads();

    const size_t wOff = (size_t)e * NI * ND;
    const float* w1e = w1 + wOff;
    const float* w3e = w3 + wOff;

    // Load mapping: each thread loads one float4 per tile per operand.
    // row lr in [0,64), k-offset lk in {0,4,8,12}.
    const int lr = tid >> 2;
    const int lk = (tid & 3) * 4;

    const int aslot = sSlot[lr];
    const float* arow  = x + (size_t)((aslot >= 0 ? aslot : 0) / NA) * ND;
    const float* b1row = w1e + (size_t)(nBase + lr) * ND;
    const float* b3row = w3e + (size_t)(nBase + lr) * ND;

    float acc1[4][4] = {};
    float acc3[4][4] = {};

    for (int kt = 0; kt < ND; kt += TK) {
        float4 av  = *(const float4*)(arow  + kt + lk);
        float4 b1v = *(const float4*)(b1row + kt + lk);
        float4 b3v = *(const float4*)(b3row + kt + lk);
        As [lk + 0][lr] = av.x;  As [lk + 1][lr] = av.y;
        As [lk + 2][lr] = av.z;  As [lk + 3][lr] = av.w;
        B1s[lk + 0][lr] = b1v.x; B1s[lk + 1][lr] = b1v.y;
        B1s[lk + 2][lr] = b1v.z; B1s[lk + 3][lr] = b1v.w;
        B3s[lk + 0][lr] = b3v.x; B3s[lk + 1][lr] = b3v.y;
        B3s[lk + 2][lr] = b3v.z; B3s[lk + 3][lr] = b3v.w;
        __syncthreads();

        #pragma unroll
        for (int k = 0; k < TK; k++) {
            float a[4], b1[4], b3[4];
            *(float4*)a  = *(const float4*)&As [k][ty * 4];
            *(float4*)b1 = *(const float4*)&B1s[k][tx * 4];
            *(float4*)b3 = *(const float4*)&B3s[k][tx * 4];
            #pragma unroll
            for (int i = 0; i < 4; i++) {
                #pragma unroll
                for (int j = 0; j < 4; j++) {
                    acc1[i][j] = fmaf(a[i], b1[j], acc1[i][j]);
                    acc3[i][j] = fmaf(a[i], b3[j], acc3[i][j]);
                }
            }
        }
        __syncthreads();
    }

    const int nx = nBase + tx * 4;
    #pragma unroll
    for (int i = 0; i < 4; i++) {
        int slot = sSlot[ty * 4 + i];
        if (slot < 0) continue;
        float* hrow = g_h + (size_t)slot * NI + nx;
        #pragma unroll
        for (int j = 0; j < 4; j++) {
            float v   = acc1[i][j];
            float sig = 1.0f / (1.0f + expf(-v));
            hrow[j]   = v * sig * acc3[i][j];
        }
    }
}

// ---------------------------------------------------------------------------
// GEMM2: out[slot, :] = h[slot, :] @ w2[e]^T   (w2[e] is [D, I] row-major)
// ---------------------------------------------------------------------------
__global__ __launch_bounds__(256) void gemm2_kernel(
    const float* __restrict__ w2,
    float* __restrict__ out)
{
    const int e     = blockIdx.z;
    const int ne    = g_count[e];
    const int mBase = blockIdx.y * TM;
    if (mBase >= ne) return;
    const int nBase = blockIdx.x * TN;   // D index

    __shared__ __align__(16) float As[TK][PAD];
    __shared__ __align__(16) float Bs[TK][PAD];
    __shared__ int sSlot[TM];

    const int tx  = threadIdx.x;
    const int ty  = threadIdx.y;
    const int tid = ty * 16 + tx;

    if (tid < TM) {
        int m = mBase + tid;
        sSlot[tid] = (m < ne) ? g_slots[e][m] : -1;
    }
    __syncthreads();

    const float* w2e = w2 + (size_t)e * ND * NI;

    const int lr = tid >> 2;
    const int lk = (tid & 3) * 4;

    const int aslot = sSlot[lr];
    const float* arow = g_h + (size_t)(aslot >= 0 ? aslot : 0) * NI;
    const float* brow = w2e + (size_t)(nBase + lr) * NI;

    float acc[4][4] = {};

    for (int kt = 0; kt < NI; kt += TK) {
        float4 av = *(const float4*)(arow + kt + lk);
        float4 bv = *(const float4*)(brow + kt + lk);
        As[lk + 0][lr] = av.x; As[lk + 1][lr] = av.y;
        As[lk + 2][lr] = av.z; As[lk + 3][lr] = av.w;
        Bs[lk + 0][lr] = bv.x; Bs[lk + 1][lr] = bv.y;
        Bs[lk + 2][lr] = bv.z; Bs[lk + 3][lr] = bv.w;
        __syncthreads();

        #pragma unroll
        for (int k = 0; k < TK; k++) {
            float a[4], b[4];
            *(float4*)a = *(const float4*)&As[k][ty * 4];
            *(float4*)b = *(const float4*)&Bs[k][tx * 4];
            #pragma unroll
            for (int i = 0; i < 4; i++) {
                #pragma unroll
                for (int j = 0; j < 4; j++)
                    acc[i][j] = fmaf(a[i], b[j], acc[i][j]);
            }
        }
        __syncthreads();
    }

    const int nx = nBase + tx * 4;
    #pragma unroll
    for (int i = 0; i < 4; i++) {
        int slot = sSlot[ty * 4 + i];
        if (slot < 0) continue;
        float* orow = out + (size_t)slot * ND + nx;
        #pragma unroll
        for (int j = 0; j < 4; j++)
            orow[j] = acc[i][j];
    }
}

// ---------------------------------------------------------------------------
// Launch. Inputs (metadata order): x, w1, w2, w3, expert_indices.
// ---------------------------------------------------------------------------
extern "C" void kernel_launch(void* const* d_in, const int* in_sizes, int n_in,
                              void* d_out, int out_size) {
    const float* x   = (const float*)d_in[0];
    const float* w1  = (const float*)d_in[1];
    const float* w2  = (const float*)d_in[2];
    const float* w3  = (const float*)d_in[3];
    const int*   idx = (const int*)d_in[4];   // int32 or int64 (detected on device)
    float* out = (float*)d_out;

    detect_and_zero_kernel<<<1, 256>>>(idx);
    route_kernel<<<NSLOT / 256, 256>>>(idx);
    gemm1_kernel<<<dim3(NI / TN, NSLOT / TM, NE), dim3(16, 16)>>>(x, w1, w3);
    gemm2_kernel<<<dim3(ND / TN, NSLOT / TM, NE), dim3(16, 16)>>>(w2, out);
}

// round 3
// speedup vs baseline: 2.3558x; 2.3558x over previous
#include <cuda_runtime.h>
#include <cuda_bf16.h>
#include <cstdint>
#include <math.h>

// Problem constants
#define NT 1024
#define NA 2
#define NE 8
#define NI 2816
#define ND 1024
#define NSLOT (NT * NA)

// GEMM tiling
#define BM 128
#define BN 128
#define BK 32                      // bf16 elems per K chunk
#define LDS_STRIDE 80              // bytes per smem tile row (32*2 padded to 80)
#define TB (128 * LDS_STRIDE)      // one tile: 128 rows x 80B = 10240 B

// ---------------------------------------------------------------------------
// Device global scratch (no allocation allowed)
// ---------------------------------------------------------------------------
__device__ int g_count[NE];
__device__ int g_slots[NE][NSLOT];
__device__ int g_is64;

__device__ __align__(16) __nv_bfloat16 g_xh[NT * ND];
__device__ __align__(16) __nv_bfloat16 g_xl[NT * ND];
__device__ __align__(16) __nv_bfloat16 g_w1h[NE * NI * ND];
__device__ __align__(16) __nv_bfloat16 g_w1l[NE * NI * ND];
__device__ __align__(16) __nv_bfloat16 g_w3h[NE * NI * ND];
__device__ __align__(16) __nv_bfloat16 g_w3l[NE * NI * ND];
__device__ __align__(16) __nv_bfloat16 g_w2h[NE * ND * NI];
__device__ __align__(16) __nv_bfloat16 g_w2l[NE * ND * NI];
__device__ __align__(16) __nv_bfloat16 g_hh[(size_t)NSLOT * NI];
__device__ __align__(16) __nv_bfloat16 g_hl[(size_t)NSLOT * NI];

// ---------------------------------------------------------------------------
// PTX helpers (base-target sm_103 features only: ldmatrix / mma.sync / cp.async)
// ---------------------------------------------------------------------------
__device__ __forceinline__ uint32_t smem_u32(const void* p) {
    uint32_t a;
    asm("{ .reg .u64 t; cvta.to.shared.u64 t, %1; cvt.u32.u64 %0, t; }"
        : "=r"(a) : "l"(p));
    return a;
}

#define LDSM4(R, addr) \
    asm volatile("ldmatrix.sync.aligned.m8n8.x4.shared.b16 {%0,%1,%2,%3}, [%4];" \
        : "=r"((R)[0]), "=r"((R)[1]), "=r"((R)[2]), "=r"((R)[3]) : "r"(addr))

#define MMA_BF16(C, A, B0, B1) \
    asm volatile("mma.sync.aligned.m16n8k16.row.col.f32.bf16.bf16.f32 " \
        "{%0,%1,%2,%3}, {%4,%5,%6,%7}, {%8,%9}, {%0,%1,%2,%3};" \
        : "+f"((C)[0]), "+f"((C)[1]), "+f"((C)[2]), "+f"((C)[3]) \
        : "r"((A)[0]), "r"((A)[1]), "r"((A)[2]), "r"((A)[3]), "r"(B0), "r"(B1))

#define CP_ASYNC16(dst, src) \
    asm volatile("cp.async.cg.shared.global [%0], [%1], 16;" :: "r"(dst), "l"(src))
#define CP_COMMIT() asm volatile("cp.async.commit_group;" ::: "memory")

__device__ __forceinline__ uint16_t bfbits(__nv_bfloat16 b) {
    return *reinterpret_cast<uint16_t*>(&b);
}
__device__ __forceinline__ void split2(float f, uint16_t& h, uint16_t& l) {
    __nv_bfloat16 bh = __float2bfloat16(f);
    __nv_bfloat16 bl = __float2bfloat16(f - __bfloat162float(bh));
    h = bfbits(bh);
    l = bfbits(bl);
}

// ---------------------------------------------------------------------------
// Routing
// ---------------------------------------------------------------------------
__global__ void detect_and_zero_kernel(const int* __restrict__ idx32) {
    __shared__ int any;
    if (threadIdx.x == 0) any = 0;
    if (threadIdx.x < NE) g_count[threadIdx.x] = 0;
    __syncthreads();
    int local = 0;
    for (int i = threadIdx.x; i < NSLOT / 2; i += blockDim.x)
        local |= idx32[2 * i + 1];
    if (local) atomicOr(&any, 1);
    __syncthreads();
    if (threadIdx.x == 0) g_is64 = (any == 0) ? 1 : 0;
}

__global__ void route_kernel(const int* __restrict__ idx32) {
    int s = blockIdx.x * blockDim.x + threadIdx.x;
    if (s < NSLOT) {
        int e = g_is64 ? idx32[2 * s] : idx32[s];
        e &= (NE - 1);
        int p = atomicAdd(&g_count[e], 1);
        g_slots[e][p] = s;
    }
}

// ---------------------------------------------------------------------------
// fp32 -> bf16 (hi, lo) split conversion
// ---------------------------------------------------------------------------
__global__ __launch_bounds__(256) void split_bf16_kernel(
    const float* __restrict__ src,
    __nv_bfloat16* __restrict__ hi,
    __nv_bfloat16* __restrict__ lo, int n4)
{
    int i = blockIdx.x * blockDim.x + threadIdx.x;
    if (i >= n4) return;
    float4 v = reinterpret_cast<const float4*>(src)[i];
    uint16_t h0, h1, h2, h3, l0, l1, l2, l3;
    split2(v.x, h0, l0);
    split2(v.y, h1, l1);
    split2(v.z, h2, l2);
    split2(v.w, h3, l3);
    uint2 hw, lw;
    hw.x = (uint32_t)h0 | ((uint32_t)h1 << 16);
    hw.y = (uint32_t)h2 | ((uint32_t)h3 << 16);
    lw.x = (uint32_t)l0 | ((uint32_t)l1 << 16);
    lw.y = (uint32_t)l2 | ((uint32_t)l3 << 16);
    reinterpret_cast<uint2*>(hi)[i] = hw;
    reinterpret_cast<uint2*>(lo)[i] = lw;
}

// ---------------------------------------------------------------------------
// GEMM1: h = silu(X @ w1[e]^T) * (X @ w3[e]^T), bf16-split HMMA.
// Tiles per stage: Ah, Al, B1h, B1l, B3h, B3l (each 128 rows x 32 bf16, pad 80B)
// smem: [0,512) sSlot | [1024, 1024+2*6*TB) stages
// ---------------------------------------------------------------------------
#define STAGE1B (6 * TB)
#define SMEM1_BYTES (1024 + 2 * STAGE1B)

__global__ __launch_bounds__(512, 1) void gemm1_tc() {
    const int e = blockIdx.z;
    const int ne = g_count[e];
    const int mBase = blockIdx.y * BM;
    if (mBase >= ne) return;
    const int nBase = blockIdx.x * BN;

    extern __shared__ char smem[];
    const uint32_t sb = smem_u32(smem);
    const int tid = threadIdx.x;
    const int wid = tid >> 5;
    const int lane = tid & 31;

    int* sSlot = reinterpret_cast<int*>(smem);
    if (tid < BM) {
        int m = mBase + tid;
        sSlot[tid] = (m < ne) ? g_slots[e][m] : -1;
    }
    __syncthreads();

    // --- producer setup: one 16B granule per thread per tile ---
    const int prow = tid >> 2;          // 0..127
    const int pcolg = tid & 3;          // x16B
    const uint32_t doff = 1024u + (uint32_t)prow * LDS_STRIDE + pcolg * 16;
    const __nv_bfloat16* src[6];
    {
        const size_t wo = (size_t)e * NI * ND;
        int s = sSlot[prow];
        int tok = (s >= 0 ? s : 0) >> 1;
        src[0] = g_xh + (size_t)tok * ND + pcolg * 8;
        src[1] = g_xl + (size_t)tok * ND + pcolg * 8;
        src[2] = g_w1h + wo + (size_t)(nBase + prow) * ND + pcolg * 8;
        src[3] = g_w1l + wo + (size_t)(nBase + prow) * ND + pcolg * 8;
        src[4] = g_w3h + wo + (size_t)(nBase + prow) * ND + pcolg * 8;
        src[5] = g_w3l + wo + (size_t)(nBase + prow) * ND + pcolg * 8;
    }

    // --- consumer setup ---
    const int warpM = wid & 3;          // 4
    const int warpN = wid >> 2;         // 4
    // A ldmatrix per-lane offset: row = warpM*32 + (lane&15), col16 = lane>>4
    const uint32_t aoff = (uint32_t)(warpM * 32 + (lane & 15)) * LDS_STRIDE
                        + (uint32_t)(lane >> 4) * 16;
    // B ldmatrix per-lane offset: row = warpN*32 + (lane&7) + ((lane>>3)&2)*4,
    //                             col16 = (lane>>3)&1
    const uint32_t boff = (uint32_t)(warpN * 32 + (lane & 7) + ((lane >> 3) & 2) * 4) * LDS_STRIDE
                        + (uint32_t)((lane >> 3) & 1) * 16;

    float acc1[2][4][4] = {};
    float acc3[2][4][4] = {};

    const int NCH = ND / BK;   // 32

    // prologue: stage 0
    #pragma unroll
    for (int t = 0; t < 6; t++)
        CP_ASYNC16(doff + sb + t * TB, src[t]);
    CP_COMMIT();

    for (int c = 0; c < NCH; c++) {
        if (c + 1 < NCH) {
            const int kt = (c + 1) * BK;
            const uint32_t stg = ((c + 1) & 1) * STAGE1B;
            #pragma unroll
            for (int t = 0; t < 6; t++)
                CP_ASYNC16(doff + sb + stg + t * TB, src[t] + kt);
            CP_COMMIT();
            asm volatile("cp.async.wait_group 1;" ::: "memory");
        } else {
            asm volatile("cp.async.wait_group 0;" ::: "memory");
        }
        __syncthreads();

        const uint32_t bb = sb + 1024u + (c & 1) * STAGE1B;
        const uint32_t tAh = bb, tAl = bb + TB;
        const uint32_t tB1h = bb + 2 * TB, tB1l = bb + 3 * TB;
        const uint32_t tB3h = bb + 4 * TB, tB3l = bb + 5 * TB;

        #pragma unroll
        for (int kb = 0; kb < 2; kb++) {
            const uint32_t ko = kb * 32;   // 16 bf16 = 32B
            uint32_t ah[2][4], al[2][4];
            #pragma unroll
            for (int mb = 0; mb < 2; mb++) {
                LDSM4(ah[mb], tAh + aoff + mb * (16 * LDS_STRIDE) + ko);
                LDSM4(al[mb], tAl + aoff + mb * (16 * LDS_STRIDE) + ko);
            }
            uint32_t b[4];
            #pragma unroll
            for (int nb2 = 0; nb2 < 2; nb2++) {
                const uint32_t no = nb2 * (16 * LDS_STRIDE);
                // B1 hi: Ah & Al terms
                LDSM4(b, tB1h + boff + no + ko);
                #pragma unroll
                for (int mb = 0; mb < 2; mb++) {
                    MMA_BF16(acc1[mb][2 * nb2],     ah[mb], b[0], b[1]);
                    MMA_BF16(acc1[mb][2 * nb2 + 1], ah[mb], b[2], b[3]);
                    MMA_BF16(acc1[mb][2 * nb2],     al[mb], b[0], b[1]);
                    MMA_BF16(acc1[mb][2 * nb2 + 1], al[mb], b[2], b[3]);
                }
                // B1 lo: Ah term
                LDSM4(b, tB1l + boff + no + ko);
                #pragma unroll
                for (int mb = 0; mb < 2; mb++) {
                    MMA_BF16(acc1[mb][2 * nb2],     ah[mb], b[0], b[1]);
                    MMA_BF16(acc1[mb][2 * nb2 + 1], ah[mb], b[2], b[3]);
                }
                // B3 hi
                LDSM4(b, tB3h + boff + no + ko);
                #pragma unroll
                for (int mb = 0; mb < 2; mb++) {
                    MMA_BF16(acc3[mb][2 * nb2],     ah[mb], b[0], b[1]);
                    MMA_BF16(acc3[mb][2 * nb2 + 1], ah[mb], b[2], b[3]);
                    MMA_BF16(acc3[mb][2 * nb2],     al[mb], b[0], b[1]);
                    MMA_BF16(acc3[mb][2 * nb2 + 1], al[mb], b[2], b[3]);
                }
                // B3 lo
                LDSM4(b, tB3l + boff + no + ko);
                #pragma unroll
                for (int mb = 0; mb < 2; mb++) {
                    MMA_BF16(acc3[mb][2 * nb2],     ah[mb], b[0], b[1]);
                    MMA_BF16(acc3[mb][2 * nb2 + 1], ah[mb], b[2], b[3]);
                }
            }
        }
        __syncthreads();
    }

    // --- epilogue: SwiGLU, split to bf16 hi/lo, direct stores ---
    const int g = lane >> 2;
    const int tg = lane & 3;
    #pragma unroll
    for (int mb = 0; mb < 2; mb++) {
        #pragma unroll
        for (int half = 0; half < 2; half++) {      // c0/c1 vs c2/c3 (rows +0 / +8)
            const int r = warpM * 32 + mb * 16 + g + half * 8;
            const int s = sSlot[r];
            if (s < 0) continue;
            #pragma unroll
            for (int nb = 0; nb < 4; nb++) {
                const float v1a = acc1[mb][nb][half * 2];
                const float v1b = acc1[mb][nb][half * 2 + 1];
                const float v3a = acc3[mb][nb][half * 2];
                const float v3b = acc3[mb][nb][half * 2 + 1];
                const float ha = v1a / (1.0f + __expf(-v1a)) * v3a;
                const float hb = v1b / (1.0f + __expf(-v1b)) * v3b;
                uint16_t hha, hla, hhb, hlb;
                split2(ha, hha, hla);
                split2(hb, hhb, hlb);
                const size_t o = (size_t)s * NI + (nBase + warpN * 32 + nb * 8 + tg * 2);
                *reinterpret_cast<uint32_t*>(g_hh + o) = (uint32_t)hha | ((uint32_t)hhb << 16);
                *reinterpret_cast<uint32_t*>(g_hl + o) = (uint32_t)hla | ((uint32_t)hlb << 16);
            }
        }
    }
}

// ---------------------------------------------------------------------------
// GEMM2: out[slot,:] = h[slot,:] @ w2[e]^T, bf16-split HMMA.
// Tiles per stage: Ah, Al, Bh, Bl
// ---------------------------------------------------------------------------
#define STAGE2B (4 * TB)
#define SMEM2_BYTES (1024 + 2 * STAGE2B)

__global__ __launch_bounds__(512, 1) void gemm2_tc(float* __restrict__ out) {
    const int e = blockIdx.z;
    const int ne = g_count[e];
    const int mBase = blockIdx.y * BM;
    if (mBase >= ne) return;
    const int nBase = blockIdx.x * BN;

    extern __shared__ char smem[];
    const uint32_t sb = smem_u32(smem);
    const int tid = threadIdx.x;
    const int wid = tid >> 5;
    const int lane = tid & 31;

    int* sSlot = reinterpret_cast<int*>(smem);
    if (tid < BM) {
        int m = mBase + tid;
        sSlot[tid] = (m < ne) ? g_slots[e][m] : -1;
    }
    __syncthreads();

    const int prow = tid >> 2;
    const int pcolg = tid & 3;
    const uint32_t doff = 1024u + (uint32_t)prow * LDS_STRIDE + pcolg * 16;
    const __nv_bfloat16* src[4];
    {
        const size_t wo = (size_t)e * ND * NI;
        int s = sSlot[prow];
        int sl = (s >= 0 ? s : 0);
        src[0] = g_hh + (size_t)sl * NI + pcolg * 8;
        src[1] = g_hl + (size_t)sl * NI + pcolg * 8;
        src[2] = g_w2h + wo + (size_t)(nBase + prow) * NI + pcolg * 8;
        src[3] = g_w2l + wo + (size_t)(nBase + prow) * NI + pcolg * 8;
    }

    const int warpM = wid & 3;
    const int warpN = wid >> 2;
    const uint32_t aoff = (uint32_t)(warpM * 32 + (lane & 15)) * LDS_STRIDE
                        + (uint32_t)(lane >> 4) * 16;
    const uint32_t boff = (uint32_t)(warpN * 32 + (lane & 7) + ((lane >> 3) & 2) * 4) * LDS_STRIDE
                        + (uint32_t)((lane >> 3) & 1) * 16;

    float acc[2][4][4] = {};

    const int NCH = NI / BK;   // 88

    #pragma unroll
    for (int t = 0; t < 4; t++)
        CP_ASYNC16(doff + sb + t * TB, src[t]);
    CP_COMMIT();

    for (int c = 0; c < NCH; c++) {
        if (c + 1 < NCH) {
            const int kt = (c + 1) * BK;
            const uint32_t stg = ((c + 1) & 1) * STAGE2B;
            #pragma unroll
            for (int t = 0; t < 4; t++)
                CP_ASYNC16(doff + sb + stg + t * TB, src[t] + kt);
            CP_COMMIT();
            asm volatile("cp.async.wait_group 1;" ::: "memory");
        } else {
            asm volatile("cp.async.wait_group 0;" ::: "memory");
        }
        __syncthreads();

        const uint32_t bb = sb + 1024u + (c & 1) * STAGE2B;
        const uint32_t tAh = bb, tAl = bb + TB;
        const uint32_t tBh = bb + 2 * TB, tBl = bb + 3 * TB;

        #pragma unroll
        for (int kb = 0; kb < 2; kb++) {
            const uint32_t ko = kb * 32;
            uint32_t ah[2][4], al[2][4];
            #pragma unroll
            for (int mb = 0; mb < 2; mb++) {
                LDSM4(ah[mb], tAh + aoff + mb * (16 * LDS_STRIDE) + ko);
                LDSM4(al[mb], tAl + aoff + mb * (16 * LDS_STRIDE) + ko);
            }
            uint32_t b[4];
            #pragma unroll
            for (int nb2 = 0; nb2 < 2; nb2++) {
                const uint32_t no = nb2 * (16 * LDS_STRIDE);
                LDSM4(b, tBh + boff + no + ko);
                #pragma unroll
                for (int mb = 0; mb < 2; mb++) {
                    MMA_BF16(acc[mb][2 * nb2],     ah[mb], b[0], b[1]);
                    MMA_BF16(acc[mb][2 * nb2 + 1], ah[mb], b[2], b[3]);
                    MMA_BF16(acc[mb][2 * nb2],     al[mb], b[0], b[1]);
                    MMA_BF16(acc[mb][2 * nb2 + 1], al[mb], b[2], b[3]);
                }
                LDSM4(b, tBl + boff + no + ko);
                #pragma unroll
                for (int mb = 0; mb < 2; mb++) {
                    MMA_BF16(acc[mb][2 * nb2],     ah[mb], b[0], b[1]);
                    MMA_BF16(acc[mb][2 * nb2 + 1], ah[mb], b[2], b[3]);
                }
            }
        }
        __syncthreads();
    }

    // --- epilogue: fp32 direct stores (float2 per c-pair) ---
    const int g = lane >> 2;
    const int tg = lane & 3;
    #pragma unroll
    for (int mb = 0; mb < 2; mb++) {
        #pragma unroll
        for (int half = 0; half < 2; half++) {
            const int r = warpM * 32 + mb * 16 + g + half * 8;
            const int s = sSlot[r];
            if (s < 0) continue;
            #pragma unroll
            for (int nb = 0; nb < 4; nb++) {
                float2 v;
                v.x = acc[mb][nb][half * 2];
                v.y = acc[mb][nb][half * 2 + 1];
                const size_t o = (size_t)s * ND + (nBase + warpN * 32 + nb * 8 + tg * 2);
                *reinterpret_cast<float2*>(out + o) = v;
            }
        }
    }
}

// ---------------------------------------------------------------------------
// Launch. Inputs (metadata order): x, w1, w2, w3, expert_indices.
// ---------------------------------------------------------------------------
extern "C" void kernel_launch(void* const* d_in, const int* in_sizes, int n_in,
                              void* d_out, int out_size) {
    const float* x  = (const float*)d_in[0];
    const float* w1 = (const float*)d_in[1];
    const float* w2 = (const float*)d_in[2];
    const float* w3 = (const float*)d_in[3];
    const int*   idx = (const int*)d_in[4];
    float* out = (float*)d_out;

    cudaFuncSetAttribute(gemm1_tc, cudaFuncAttributeMaxDynamicSharedMemorySize, SMEM1_BYTES);
    cudaFuncSetAttribute(gemm2_tc, cudaFuncAttributeMaxDynamicSharedMemorySize, SMEM2_BYTES);

    __nv_bfloat16 *xh, *xl, *w1h, *w1l, *w2h, *w2l, *w3h, *w3l;
    cudaGetSymbolAddress((void**)&xh,  g_xh);
    cudaGetSymbolAddress((void**)&xl,  g_xl);
    cudaGetSymbolAddress((void**)&w1h, g_w1h);
    cudaGetSymbolAddress((void**)&w1l, g_w1l);
    cudaGetSymbolAddress((void**)&w2h, g_w2h);
    cudaGetSymbolAddress((void**)&w2l, g_w2l);
    cudaGetSymbolAddress((void**)&w3h, g_w3h);
    cudaGetSymbolAddress((void**)&w3l, g_w3l);

    detect_and_zero_kernel<<<1, 256>>>(idx);
    route_kernel<<<NSLOT / 256, 256>>>(idx);

    const int nW4 = NE * NI * ND / 4;
    const int nX4 = NT * ND / 4;
    split_bf16_kernel<<<nX4 / 256, 256>>>(x,  xh,  xl,  nX4);
    split_bf16_kernel<<<nW4 / 256, 256>>>(w1, w1h, w1l, nW4);
    split_bf16_kernel<<<nW4 / 256, 256>>>(w2, w2h, w2l, nW4);
    split_bf16_kernel<<<nW4 / 256, 256>>>(w3, w3h, w3l, nW4);

    gemm1_tc<<<dim3(NI / BN, NSLOT / BM, NE), 512, SMEM1_BYTES>>>();
    gemm2_tc<<<dim3(ND / BN, NSLOT / BM, NE), 512, SMEM2_BYTES>>>(out);
}

// round 4
// speedup vs baseline: 2.6409x; 1.1210x over previous
#include <cuda_runtime.h>
#include <cuda_bf16.h>
#include <cstdint>
#include <math.h>

// Problem constants
#define NT 1024
#define NA 2
#define NE 8
#define NI 2816
#define ND 1024
#define NSLOT (NT * NA)

// GEMM tiling
#define BM 128
#define BN 128
#define BK 32                      // bf16 elems per K chunk
#define LDS_STRIDE 80              // bytes per smem tile row (32*2 padded to 80)
#define TB (128 * LDS_STRIDE)      // one tile: 128 rows x 80B = 10240 B

// ---------------------------------------------------------------------------
// Device global scratch (no allocation allowed)
// ---------------------------------------------------------------------------
__device__ int g_count[NE];
__device__ int g_slots[NE][NSLOT];
__device__ int g_is64;

__device__ __align__(16) __nv_bfloat16 g_xh[NT * ND];
__device__ __align__(16) __nv_bfloat16 g_xl[NT * ND];
__device__ __align__(16) __nv_bfloat16 g_hh[(size_t)NSLOT * NI];
__device__ __align__(16) __nv_bfloat16 g_hl[(size_t)NSLOT * NI];

// ---------------------------------------------------------------------------
// PTX helpers (base-target sm_103 features only: ldmatrix / mma.sync / cp.async)
// ---------------------------------------------------------------------------
__device__ __forceinline__ uint32_t smem_u32(const void* p) {
    uint32_t a;
    asm("{ .reg .u64 t; cvta.to.shared.u64 t, %1; cvt.u32.u64 %0, t; }"
        : "=r"(a) : "l"(p));
    return a;
}

#define LDSM4(R, addr) \
    asm volatile("ldmatrix.sync.aligned.m8n8.x4.shared.b16 {%0,%1,%2,%3}, [%4];" \
        : "=r"((R)[0]), "=r"((R)[1]), "=r"((R)[2]), "=r"((R)[3]) : "r"(addr))

#define MMA_BF16(C, A, B0, B1) \
    asm volatile("mma.sync.aligned.m16n8k16.row.col.f32.bf16.bf16.f32 " \
        "{%0,%1,%2,%3}, {%4,%5,%6,%7}, {%8,%9}, {%0,%1,%2,%3};" \
        : "+f"((C)[0]), "+f"((C)[1]), "+f"((C)[2]), "+f"((C)[3]) \
        : "r"((A)[0]), "r"((A)[1]), "r"((A)[2]), "r"((A)[3]), "r"(B0), "r"(B1))

#define CP_ASYNC16(dst, src) \
    asm volatile("cp.async.cg.shared.global [%0], [%1], 16;" :: "r"(dst), "l"(src))
#define CP_COMMIT() asm volatile("cp.async.commit_group;" ::: "memory")

__device__ __forceinline__ uint16_t bfbits(__nv_bfloat16 b) {
    return *reinterpret_cast<uint16_t*>(&b);
}
__device__ __forceinline__ void split2(float f, uint16_t& h, uint16_t& l) {
    __nv_bfloat16 bh = __float2bfloat16(f);
    __nv_bfloat16 bl = __float2bfloat16(f - __bfloat162float(bh));
    h = bfbits(bh);
    l = bfbits(bl);
}

// Convert 8 fp32 (2x float4) -> 4 u32 of packed bf16-hi and 4 u32 of bf16-lo
__device__ __forceinline__ void split8(const float4& a, const float4& b,
                                       uint4& hw, uint4& lw) {
    uint16_t h0, h1, l0, l1;
    split2(a.x, h0, l0); split2(a.y, h1, l1);
    hw.x = (uint32_t)h0 | ((uint32_t)h1 << 16);
    lw.x = (uint32_t)l0 | ((uint32_t)l1 << 16);
    split2(a.z, h0, l0); split2(a.w, h1, l1);
    hw.y = (uint32_t)h0 | ((uint32_t)h1 << 16);
    lw.y = (uint32_t)l0 | ((uint32_t)l1 << 16);
    split2(b.x, h0, l0); split2(b.y, h1, l1);
    hw.z = (uint32_t)h0 | ((uint32_t)h1 << 16);
    lw.z = (uint32_t)l0 | ((uint32_t)l1 << 16);
    split2(b.z, h0, l0); split2(b.w, h1, l1);
    hw.w = (uint32_t)h0 | ((uint32_t)h1 << 16);
    lw.w = (uint32_t)l0 | ((uint32_t)l1 << 16);
}

// ---------------------------------------------------------------------------
// Routing
// ---------------------------------------------------------------------------
__global__ void detect_and_zero_kernel(const int* __restrict__ idx32) {
    __shared__ int any;
    if (threadIdx.x == 0) any = 0;
    if (threadIdx.x < NE) g_count[threadIdx.x] = 0;
    __syncthreads();
    int local = 0;
    for (int i = threadIdx.x; i < NSLOT / 2; i += blockDim.x)
        local |= idx32[2 * i + 1];
    if (local) atomicOr(&any, 1);
    __syncthreads();
    if (threadIdx.x == 0) g_is64 = (any == 0) ? 1 : 0;
}

__global__ void route_kernel(const int* __restrict__ idx32) {
    int s = blockIdx.x * blockDim.x + threadIdx.x;
    if (s < NSLOT) {
        int e = g_is64 ? idx32[2 * s] : idx32[s];
        e &= (NE - 1);
        int p = atomicAdd(&g_count[e], 1);
        g_slots[e][p] = s;
    }
}

// ---------------------------------------------------------------------------
// x: fp32 -> bf16 (hi, lo) split conversion (small: 4 MB read)
// ---------------------------------------------------------------------------
__global__ __launch_bounds__(256) void split_bf16_kernel(
    const float* __restrict__ src,
    __nv_bfloat16* __restrict__ hi,
    __nv_bfloat16* __restrict__ lo, int n4)
{
    int i = blockIdx.x * blockDim.x + threadIdx.x;
    if (i >= n4) return;
    float4 v = reinterpret_cast<const float4*>(src)[i];
    uint16_t h0, h1, h2, h3, l0, l1, l2, l3;
    split2(v.x, h0, l0);
    split2(v.y, h1, l1);
    split2(v.z, h2, l2);
    split2(v.w, h3, l3);
    uint2 hw, lw;
    hw.x = (uint32_t)h0 | ((uint32_t)h1 << 16);
    hw.y = (uint32_t)h2 | ((uint32_t)h3 << 16);
    lw.x = (uint32_t)l0 | ((uint32_t)l1 << 16);
    lw.y = (uint32_t)l2 | ((uint32_t)l3 << 16);
    reinterpret_cast<uint2*>(hi)[i] = hw;
    reinterpret_cast<uint2*>(lo)[i] = lw;
}

// ---------------------------------------------------------------------------
// GEMM1: h = silu(X @ w1[e]^T) * (X @ w3[e]^T), bf16-split HMMA.
// Weights converted fp32->bf16 hi/lo IN the producer (register-staged).
// Stage tiles: Ah, Al, B1h, B1l, B3h, B3l (each 128 rows x 32 bf16, pad 80B)
// smem: [0,512) sSlot | [1024, 1024+2*6*TB) stages
// ---------------------------------------------------------------------------
#define STAGE1B (6 * TB)
#define SMEM1_BYTES (1024 + 2 * STAGE1B)

__global__ __launch_bounds__(512, 1) void gemm1_tc(
    const float* __restrict__ w1, const float* __restrict__ w3)
{
    const int e = blockIdx.z;
    const int ne = g_count[e];
    const int mBase = blockIdx.y * BM;
    if (mBase >= ne) return;
    const int nBase = blockIdx.x * BN;

    extern __shared__ char smem[];
    const uint32_t sb = smem_u32(smem);
    const int tid = threadIdx.x;
    const int wid = tid >> 5;
    const int lane = tid & 31;

    int* sSlot = reinterpret_cast<int*>(smem);
    if (tid < BM) {
        int m = mBase + tid;
        sSlot[tid] = (m < ne) ? g_slots[e][m] : -1;
    }
    __syncthreads();

    // --- A producer (cp.async, pre-split x): one 16B granule per tile ---
    const int prow = tid >> 2;          // 0..127
    const int pcolg = tid & 3;          // x16B
    const uint32_t adoff = 1024u + (uint32_t)prow * LDS_STRIDE + pcolg * 16;
    const __nv_bfloat16* asrc[2];
    {
        int s = sSlot[prow];
        int tok = (s >= 0 ? s : 0) >> 1;
        asrc[0] = g_xh + (size_t)tok * ND + pcolg * 8;
        asrc[1] = g_xl + (size_t)tok * ND + pcolg * 8;
    }

    // --- W producer (fused conversion): 16 fp32 per thread per chunk ---
    // 512 threads cover 2 tiles (w1, w3) x 128 rows x 32 cols
    const int wt    = tid >> 8;            // 0: w1, 1: w3
    const int wrow  = (tid & 255) >> 1;    // 0..127
    const int whalf = tid & 1;             // 16 floats each
    const float* wsrc = (wt == 0 ? w1 : w3)
        + (size_t)e * NI * ND + (size_t)(nBase + wrow) * ND + whalf * 16;
    const uint32_t wdoff = (uint32_t)wrow * LDS_STRIDE + whalf * 32;
    const uint32_t wtile_h = 1024u + (uint32_t)(2 + wt * 2) * TB;  // B1h or B3h
    const uint32_t wtile_l = wtile_h + TB;

    // --- consumer setup ---
    const int warpM = wid & 3;
    const int warpN = wid >> 2;
    const uint32_t aoff = (uint32_t)(warpM * 32 + (lane & 15)) * LDS_STRIDE
                        + (uint32_t)(lane >> 4) * 16;
    const uint32_t boff = (uint32_t)(warpN * 32 + (lane & 7) + ((lane >> 3) & 2) * 4) * LDS_STRIDE
                        + (uint32_t)((lane >> 3) & 1) * 16;

    float acc1[2][4][4] = {};
    float acc3[2][4][4] = {};

    const int NCH = ND / BK;   // 32

    // --- prologue: fill stage 0 ---
    CP_ASYNC16(adoff + sb, asrc[0]);
    CP_ASYNC16(adoff + sb + TB, asrc[1]);
    CP_COMMIT();
    {
        float4 s0 = *reinterpret_cast<const float4*>(wsrc + 0);
        float4 s1 = *reinterpret_cast<const float4*>(wsrc + 4);
        float4 s2 = *reinterpret_cast<const float4*>(wsrc + 8);
        float4 s3 = *reinterpret_cast<const float4*>(wsrc + 12);
        uint4 hw, lw;
        split8(s0, s1, hw, lw);
        *reinterpret_cast<uint4*>(smem + wtile_h + wdoff) = hw;
        *reinterpret_cast<uint4*>(smem + wtile_l + wdoff) = lw;
        split8(s2, s3, hw, lw);
        *reinterpret_cast<uint4*>(smem + wtile_h + wdoff + 16) = hw;
        *reinterpret_cast<uint4*>(smem + wtile_l + wdoff + 16) = lw;
    }

    for (int c = 0; c < NCH; c++) {
        float4 s0, s1, s2, s3;
        if (c + 1 < NCH) {
            const int kt = (c + 1) * BK;
            // stage weights for next chunk in registers (latency hidden by MMAs)
            s0 = *reinterpret_cast<const float4*>(wsrc + kt + 0);
            s1 = *reinterpret_cast<const float4*>(wsrc + kt + 4);
            s2 = *reinterpret_cast<const float4*>(wsrc + kt + 8);
            s3 = *reinterpret_cast<const float4*>(wsrc + kt + 12);
            const uint32_t stg = ((c + 1) & 1) * STAGE1B;
            CP_ASYNC16(adoff + sb + stg, asrc[0] + kt);
            CP_ASYNC16(adoff + sb + stg + TB, asrc[1] + kt);
            CP_COMMIT();
            asm volatile("cp.async.wait_group 1;" ::: "memory");
        } else {
            asm volatile("cp.async.wait_group 0;" ::: "memory");
        }
        __syncthreads();

        const uint32_t bb = sb + 1024u + (c & 1) * STAGE1B;
        const uint32_t tAh = bb, tAl = bb + TB;
        const uint32_t tB1h = bb + 2 * TB, tB1l = bb + 3 * TB;
        const uint32_t tB3h = bb + 4 * TB, tB3l = bb + 5 * TB;

        #pragma unroll
        for (int kb = 0; kb < 2; kb++) {
            const uint32_t ko = kb * 32;   // 16 bf16 = 32B
            uint32_t ah[2][4], al[2][4];
            #pragma unroll
            for (int mb = 0; mb < 2; mb++) {
                LDSM4(ah[mb], tAh + aoff + mb * (16 * LDS_STRIDE) + ko);
                LDSM4(al[mb], tAl + aoff + mb * (16 * LDS_STRIDE) + ko);
            }
            uint32_t b[4];
            #pragma unroll
            for (int nb2 = 0; nb2 < 2; nb2++) {
                const uint32_t no = nb2 * (16 * LDS_STRIDE);
                LDSM4(b, tB1h + boff + no + ko);
                #pragma unroll
                for (int mb = 0; mb < 2; mb++) {
                    MMA_BF16(acc1[mb][2 * nb2],     ah[mb], b[0], b[1]);
                    MMA_BF16(acc1[mb][2 * nb2 + 1], ah[mb], b[2], b[3]);
                    MMA_BF16(acc1[mb][2 * nb2],     al[mb], b[0], b[1]);
                    MMA_BF16(acc1[mb][2 * nb2 + 1], al[mb], b[2], b[3]);
                }
                LDSM4(b, tB1l + boff + no + ko);
                #pragma unroll
                for (int mb = 0; mb < 2; mb++) {
                    MMA_BF16(acc1[mb][2 * nb2],     ah[mb], b[0], b[1]);
                    MMA_BF16(acc1[mb][2 * nb2 + 1], ah[mb], b[2], b[3]);
                }
                LDSM4(b, tB3h + boff + no + ko);
                #pragma unroll
                for (int mb = 0; mb < 2; mb++) {
                    MMA_BF16(acc3[mb][2 * nb2],     ah[mb], b[0], b[1]);
                    MMA_BF16(acc3[mb][2 * nb2 + 1], ah[mb], b[2], b[3]);
                    MMA_BF16(acc3[mb][2 * nb2],     al[mb], b[0], b[1]);
                    MMA_BF16(acc3[mb][2 * nb2 + 1], al[mb], b[2], b[3]);
                }
                LDSM4(b, tB3l + boff + no + ko);
                #pragma unroll
                for (int mb = 0; mb < 2; mb++) {
                    MMA_BF16(acc3[mb][2 * nb2],     ah[mb], b[0], b[1]);
                    MMA_BF16(acc3[mb][2 * nb2 + 1], ah[mb], b[2], b[3]);
                }
            }
        }

        if (c + 1 < NCH) {
            const uint32_t stg = ((c + 1) & 1) * STAGE1B;
            uint4 hw, lw;
            split8(s0, s1, hw, lw);
            *reinterpret_cast<uint4*>(smem + wtile_h + stg + wdoff) = hw;
            *reinterpret_cast<uint4*>(smem + wtile_l + stg + wdoff) = lw;
            split8(s2, s3, hw, lw);
            *reinterpret_cast<uint4*>(smem + wtile_h + stg + wdoff + 16) = hw;
            *reinterpret_cast<uint4*>(smem + wtile_l + stg + wdoff + 16) = lw;
        }
        __syncthreads();
    }

    // --- epilogue: SwiGLU, split to bf16 hi/lo, direct stores ---
    const int g = lane >> 2;
    const int tg = lane & 3;
    #pragma unroll
    for (int mb = 0; mb < 2; mb++) {
        #pragma unroll
        for (int half = 0; half < 2; half++) {
            const int r = warpM * 32 + mb * 16 + g + half * 8;
            const int s = sSlot[r];
            if (s < 0) continue;
            #pragma unroll
            for (int nb = 0; nb < 4; nb++) {
                const float v1a = acc1[mb][nb][half * 2];
                const float v1b = acc1[mb][nb][half * 2 + 1];
                const float v3a = acc3[mb][nb][half * 2];
                const float v3b = acc3[mb][nb][half * 2 + 1];
                const float ha = v1a / (1.0f + __expf(-v1a)) * v3a;
                const float hb = v1b / (1.0f + __expf(-v1b)) * v3b;
                uint16_t hha, hla, hhb, hlb;
                split2(ha, hha, hla);
                split2(hb, hhb, hlb);
                const size_t o = (size_t)s * NI + (nBase + warpN * 32 + nb * 8 + tg * 2);
                *reinterpret_cast<uint32_t*>(g_hh + o) = (uint32_t)hha | ((uint32_t)hhb << 16);
                *reinterpret_cast<uint32_t*>(g_hl + o) = (uint32_t)hla | ((uint32_t)hlb << 16);
            }
        }
    }
}

// ---------------------------------------------------------------------------
// GEMM2: out[slot,:] = h[slot,:] @ w2[e]^T, bf16-split HMMA.
// w2 converted fp32->bf16 hi/lo in producer. Stage tiles: Ah, Al, Bh, Bl.
// ---------------------------------------------------------------------------
#define STAGE2B (4 * TB)
#define SMEM2_BYTES (1024 + 2 * STAGE2B)

__global__ __launch_bounds__(512, 1) void gemm2_tc(
    const float* __restrict__ w2, float* __restrict__ out)
{
    const int e = blockIdx.z;
    const int ne = g_count[e];
    const int mBase = blockIdx.y * BM;
    if (mBase >= ne) return;
    const int nBase = blockIdx.x * BN;

    extern __shared__ char smem[];
    const uint32_t sb = smem_u32(smem);
    const int tid = threadIdx.x;
    const int wid = tid >> 5;
    const int lane = tid & 31;

    int* sSlot = reinterpret_cast<int*>(smem);
    if (tid < BM) {
        int m = mBase + tid;
        sSlot[tid] = (m < ne) ? g_slots[e][m] : -1;
    }
    __syncthreads();

    // --- A producer (cp.async from h hi/lo) ---
    const int prow = tid >> 2;
    const int pcolg = tid & 3;
    const uint32_t adoff = 1024u + (uint32_t)prow * LDS_STRIDE + pcolg * 16;
    const __nv_bfloat16* asrc[2];
    {
        int s = sSlot[prow];
        int sl = (s >= 0 ? s : 0);
        asrc[0] = g_hh + (size_t)sl * NI + pcolg * 8;
        asrc[1] = g_hl + (size_t)sl * NI + pcolg * 8;
    }

    // --- W producer: 8 fp32 per thread per chunk (1 tile: 128x32) ---
    const int wrow = tid >> 2;           // 0..127
    const int wq   = tid & 3;            // 8 floats each
    const float* wsrc = w2 + (size_t)e * ND * NI + (size_t)(nBase + wrow) * NI + wq * 8;
    const uint32_t wdoff = (uint32_t)wrow * LDS_STRIDE + wq * 16;
    const uint32_t wtile_h = 1024u + 2u * TB;
    const uint32_t wtile_l = wtile_h + TB;

    const int warpM = wid & 3;
    const int warpN = wid >> 2;
    const uint32_t aoff = (uint32_t)(warpM * 32 + (lane & 15)) * LDS_STRIDE
                        + (uint32_t)(lane >> 4) * 16;
    const uint32_t boff = (uint32_t)(warpN * 32 + (lane & 7) + ((lane >> 3) & 2) * 4) * LDS_STRIDE
                        + (uint32_t)((lane >> 3) & 1) * 16;

    float acc[2][4][4] = {};

    const int NCH = NI / BK;   // 88

    // --- prologue ---
    CP_ASYNC16(adoff + sb, asrc[0]);
    CP_ASYNC16(adoff + sb + TB, asrc[1]);
    CP_COMMIT();
    {
        float4 s0 = *reinterpret_cast<const float4*>(wsrc + 0);
        float4 s1 = *reinterpret_cast<const float4*>(wsrc + 4);
        uint4 hw, lw;
        split8(s0, s1, hw, lw);
        *reinterpret_cast<uint4*>(smem + wtile_h + wdoff) = hw;
        *reinterpret_cast<uint4*>(smem + wtile_l + wdoff) = lw;
    }

    for (int c = 0; c < NCH; c++) {
        float4 s0, s1;
        if (c + 1 < NCH) {
            const int kt = (c + 1) * BK;
            s0 = *reinterpret_cast<const float4*>(wsrc + kt + 0);
            s1 = *reinterpret_cast<const float4*>(wsrc + kt + 4);
            const uint32_t stg = ((c + 1) & 1) * STAGE2B;
            CP_ASYNC16(adoff + sb + stg, asrc[0] + kt);
            CP_ASYNC16(adoff + sb + stg + TB, asrc[1] + kt);
            CP_COMMIT();
            asm volatile("cp.async.wait_group 1;" ::: "memory");
        } else {
            asm volatile("cp.async.wait_group 0;" ::: "memory");
        }
        __syncthreads();

        const uint32_t bb = sb + 1024u + (c & 1) * STAGE2B;
        const uint32_t tAh = bb, tAl = bb + TB;
        const uint32_t tBh = bb + 2 * TB, tBl = bb + 3 * TB;

        #pragma unroll
        for (int kb = 0; kb < 2; kb++) {
            const uint32_t ko = kb * 32;
            uint32_t ah[2][4], al[2][4];
            #pragma unroll
            for (int mb = 0; mb < 2; mb++) {
                LDSM4(ah[mb], tAh + aoff + mb * (16 * LDS_STRIDE) + ko);
                LDSM4(al[mb], tAl + aoff + mb * (16 * LDS_STRIDE) + ko);
            }
            uint32_t b[4];
            #pragma unroll
            for (int nb2 = 0; nb2 < 2; nb2++) {
                const uint32_t no = nb2 * (16 * LDS_STRIDE);
                LDSM4(b, tBh + boff + no + ko);
                #pragma unroll
                for (int mb = 0; mb < 2; mb++) {
                    MMA_BF16(acc[mb][2 * nb2],     ah[mb], b[0], b[1]);
                    MMA_BF16(acc[mb][2 * nb2 + 1], ah[mb], b[2], b[3]);
                    MMA_BF16(acc[mb][2 * nb2],     al[mb], b[0], b[1]);
                    MMA_BF16(acc[mb][2 * nb2 + 1], al[mb], b[2], b[3]);
                }
                LDSM4(b, tBl + boff + no + ko);
                #pragma unroll
                for (int mb = 0; mb < 2; mb++) {
                    MMA_BF16(acc[mb][2 * nb2],     ah[mb], b[0], b[1]);
                    MMA_BF16(acc[mb][2 * nb2 + 1], ah[mb], b[2], b[3]);
                }
            }
        }

        if (c + 1 < NCH) {
            const uint32_t stg = ((c + 1) & 1) * STAGE2B;
            uint4 hw, lw;
            split8(s0, s1, hw, lw);
            *reinterpret_cast<uint4*>(smem + wtile_h + stg + wdoff) = hw;
            *reinterpret_cast<uint4*>(smem + wtile_l + stg + wdoff) = lw;
        }
        __syncthreads();
    }

    // --- epilogue: fp32 direct stores ---
    const int g = lane >> 2;
    const int tg = lane & 3;
    #pragma unroll
    for (int mb = 0; mb < 2; mb++) {
        #pragma unroll
        for (int half = 0; half < 2; half++) {
            const int r = warpM * 32 + mb * 16 + g + half * 8;
            const int s = sSlot[r];
            if (s < 0) continue;
            #pragma unroll
            for (int nb = 0; nb < 4; nb++) {
                float2 v;
                v.x = acc[mb][nb][half * 2];
                v.y = acc[mb][nb][half * 2 + 1];
                const size_t o = (size_t)s * ND + (nBase + warpN * 32 + nb * 8 + tg * 2);
                *reinterpret_cast<float2*>(out + o) = v;
            }
        }
    }
}

// ---------------------------------------------------------------------------
// Launch. Inputs (metadata order): x, w1, w2, w3, expert_indices.
// ---------------------------------------------------------------------------
extern "C" void kernel_launch(void* const* d_in, const int* in_sizes, int n_in,
                              void* d_out, int out_size) {
    const float* x  = (const float*)d_in[0];
    const float* w1 = (const float*)d_in[1];
    const float* w2 = (const float*)d_in[2];
    const float* w3 = (const float*)d_in[3];
    const int*   idx = (const int*)d_in[4];
    float* out = (float*)d_out;

    cudaFuncSetAttribute(gemm1_tc, cudaFuncAttributeMaxDynamicSharedMemorySize, SMEM1_BYTES);
    cudaFuncSetAttribute(gemm2_tc, cudaFuncAttributeMaxDynamicSharedMemorySize, SMEM2_BYTES);

    __nv_bfloat16 *xh, *xl;
    cudaGetSymbolAddress((void**)&xh, g_xh);
    cudaGetSymbolAddress((void**)&xl, g_xl);

    detect_and_zero_kernel<<<1, 256>>>(idx);
    route_kernel<<<NSLOT / 256, 256>>>(idx);

    const int nX4 = NT * ND / 4;
    split_bf16_kernel<<<nX4 / 256, 256>>>(x, xh, xl, nX4);

    gemm1_tc<<<dim3(NI / BN, NSLOT / BM, NE), 512, SMEM1_BYTES>>>(w1, w3);
    gemm2_tc<<<dim3(ND / BN, NSLOT / BM, NE), 512, SMEM2_BYTES>>>(w2, out);
}